// round 2
// baseline (speedup 1.0000x reference)
#include <cuda_runtime.h>
#include <cstdint>

#define DV 16
#define HV 64
#define WV 64
#define NVOX (DV*HV*WV)   /* 65536 voxels */
#define JP   64           /* padded channel count (>= J=55) */

// Scratch (no allocations allowed): transposed voxel [voxel][JP] and transposed lbsw [J][N]
__device__ __align__(16) float g_vol_t[NVOX * JP];   // 16 MB
__device__ float g_lbsw_t[56 * 262144];              // fits 55 * 250000
__device__ int   g_mask_is_u8;                        // runtime mask-dtype flag

// ---------------------------------------------------------------------------
// Kernel 0a/0b: mask dtype detection. If the mask buffer is int32 (values 0/1),
// every byte at offset %4 != 0 is zero. If it's bool/u8 (random 0/1), some
// byte at a non-aligned offset is 1 with overwhelming probability.
// ---------------------------------------------------------------------------
__global__ void reset_flag_kernel() { g_mask_is_u8 = 0; }

__global__ void detect_mask_kernel(const unsigned char* __restrict__ m, int N) {
    int i = blockIdx.x * 256 + threadIdx.x;
    int limit = N < 65536 ? N : 65536;   // N bytes are safe under both layouts
    if (i < limit && (i & 3) != 0 && m[i] != 0)
        atomicOr(&g_mask_is_u8, 1);
}

// ---------------------------------------------------------------------------
// Kernel 1: vol [J][D][H][W] -> g_vol_t [D*H*W][JP] (channel-contiguous, padded)
// ---------------------------------------------------------------------------
__global__ void __launch_bounds__(256) transpose_vol_kernel(const float* __restrict__ vol, int J) {
    __shared__ float tile[64][65];
    int v0 = blockIdx.x * 64;
    #pragma unroll
    for (int e = threadIdx.x; e < 64 * 64; e += 256) {
        int j = e >> 6, vi = e & 63;
        tile[j][vi] = (j < J) ? vol[j * NVOX + v0 + vi] : 0.0f;  // coalesced read per j-row
    }
    __syncthreads();
    #pragma unroll
    for (int e = threadIdx.x; e < 64 * 64; e += 256) {
        int vi = e >> 6, j = e & 63;
        g_vol_t[(v0 + vi) * JP + j] = tile[j][vi];               // coalesced write
    }
}

// ---------------------------------------------------------------------------
// Kernel 2: lbsw [N][J] -> g_lbsw_t [J][N]  (so masked-point reads coalesce)
// ---------------------------------------------------------------------------
__global__ void __launch_bounds__(256) transpose_lbsw_kernel(const float* __restrict__ lbsw, int N, int J) {
    __shared__ float tile[64][57];
    int n0 = blockIdx.x * 64;
    int cnt = min(64, N - n0);
    for (int e = threadIdx.x; e < cnt * J; e += 256) {
        int ni = e / J, j = e - ni * J;
        tile[ni][j] = lbsw[(long)n0 * J + e];                    // fully coalesced read
    }
    __syncthreads();
    for (int e = threadIdx.x; e < J * 64; e += 256) {
        int j = e >> 6, ni = e & 63;
        if (n0 + ni < N)
            g_lbsw_t[(long)j * N + n0 + ni] = tile[ni][j];       // coalesced write per j
    }
}

// ---------------------------------------------------------------------------
// Kernel 3: fused deformer, one thread per (b, n) point
// ---------------------------------------------------------------------------
static __device__ __forceinline__ float4 fma4(float a, float4 b, float4 c) {
    float4 r;
    r.x = fmaf(a, b.x, c.x); r.y = fmaf(a, b.y, c.y);
    r.z = fmaf(a, b.z, c.z); r.w = fmaf(a, b.w, c.w);
    return r;
}

#define ACC(WJ, T) do { float ww = (WJ);                                      \
    A0 = fma4(ww, s_ti[(T)+0], A0); A1 = fma4(ww, s_ti[(T)+1], A1);           \
    A2 = fma4(ww, s_ti[(T)+2], A2); A3 = fma4(ww, s_ti[(T)+3], A3);           \
    C0 = fma4(ww, s_tf[(T)+0], C0); C1 = fma4(ww, s_tf[(T)+1], C1);           \
    C2 = fma4(ww, s_tf[(T)+2], C2); C3 = fma4(ww, s_tf[(T)+3], C3); } while(0)

__global__ void __launch_bounds__(256) deform_kernel(
    const float* __restrict__ xc, const float* __restrict__ shape_off,
    const float* __restrict__ pose_off, const float* __restrict__ tfs,
    const float* __restrict__ tfs_inv, const float* __restrict__ poseoff_ori,
    const void* __restrict__ mask_raw,
    const float* __restrict__ offk, const float* __restrict__ sclk,
    float* __restrict__ out_xd, float* __restrict__ out_w,
    int N, int J)
{
    const int b = blockIdx.y;
    __shared__ float4 s_ti[56 * 4];   // tfs_inv rows (float4 per row)
    __shared__ float4 s_tf[56 * 4];   // tfs[b] rows
    {
        float* sti = (float*)s_ti;
        float* stf = (float*)s_tf;
        for (int e = threadIdx.x; e < 56 * 16; e += 256) {
            int j = e >> 4, k = e & 15;
            sti[e] = (j < J) ? tfs_inv[j * 16 + k] : 0.0f;
            stf[e] = (j < J) ? tfs[(b * J + j) * 16 + k] : 0.0f;
        }
    }
    __syncthreads();

    const int n = blockIdx.x * 256 + threadIdx.x;
    if (n >= N) return;
    const long idx = (long)b * N + n;

    const float px = xc[idx * 3 + 0], py = xc[idx * 3 + 1], pz = xc[idx * 3 + 2];
    const float fx = (px + offk[0]) * sclk[0];   // x -> W
    const float fy = (py + offk[1]) * sclk[1];   // y -> H
    const float fz = (pz + offk[2]) * sclk[2];   // z -> D

    float ix = fminf(fmaxf((fx + 1.0f) * 0.5f * (float)(WV - 1), 0.0f), (float)(WV - 1));
    float iy = fminf(fmaxf((fy + 1.0f) * 0.5f * (float)(HV - 1), 0.0f), (float)(HV - 1));
    float iz = fminf(fmaxf((fz + 1.0f) * 0.5f * (float)(DV - 1), 0.0f), (float)(DV - 1));
    float xf = floorf(ix), yf = floorf(iy), zf = floorf(iz);
    float wx = ix - xf, wy = iy - yf, wz = iz - zf;
    int x0 = (int)xf, y0 = (int)yf, z0 = (int)zf;
    int x1 = min(x0 + 1, WV - 1), y1 = min(y0 + 1, HV - 1), z1 = min(z0 + 1, DV - 1);

    int r00 = (z0 * HV + y0) * WV, r01 = (z0 * HV + y1) * WV;
    int r10 = (z1 * HV + y0) * WV, r11 = (z1 * HV + y1) * WV;
    // float4 offsets: JP(=64) floats per voxel = 16 float4 per voxel
    int o000 = (r00 + x0) * 16, o001 = (r00 + x1) * 16;
    int o010 = (r01 + x0) * 16, o011 = (r01 + x1) * 16;
    int o100 = (r10 + x0) * 16, o101 = (r10 + x1) * 16;
    int o110 = (r11 + x0) * 16, o111 = (r11 + x1) * 16;

    float mx = 1.0f - wx, my = 1.0f - wy, mz = 1.0f - wz;
    float w000 = mz * my * mx, w001 = mz * my * wx;
    float w010 = mz * wy * mx, w011 = mz * wy * wx;
    float w100 = wz * my * mx, w101 = wz * my * wx;
    float w110 = wz * wy * mx, w111 = wz * wy * wx;

    const float4* vt = (const float4*)g_vol_t;

    // Robust mask read: dtype chosen by the runtime detection flag.
    bool msk;
    if (g_mask_is_u8) {
        msk = (((const unsigned char*)mask_raw)[n] != 0);
    } else {
        msk = (((const int*)mask_raw)[n] != 0);
    }

    float4 A0 = {0,0,0,0}, A1 = {0,0,0,0}, A2 = {0,0,0,0}, A3 = {0,0,0,0};
    float4 C0 = {0,0,0,0}, C1 = {0,0,0,0}, C2 = {0,0,0,0}, C3 = {0,0,0,0};

    #pragma unroll
    for (int c = 0; c < 14; ++c) {
        float4 w4;
        if (!msk) {
            float4 va = vt[o000 + c], vb = vt[o001 + c];
            float4 vc = vt[o010 + c], vd = vt[o011 + c];
            float4 ve = vt[o100 + c], vf = vt[o101 + c];
            float4 vg = vt[o110 + c], vh = vt[o111 + c];
            w4.x = w000*va.x + w001*vb.x + w010*vc.x + w011*vd.x
                 + w100*ve.x + w101*vf.x + w110*vg.x + w111*vh.x;
            w4.y = w000*va.y + w001*vb.y + w010*vc.y + w011*vd.y
                 + w100*ve.y + w101*vf.y + w110*vg.y + w111*vh.y;
            w4.z = w000*va.z + w001*vb.z + w010*vc.z + w011*vd.z
                 + w100*ve.z + w101*vf.z + w110*vg.z + w111*vh.z;
            w4.w = w000*va.w + w001*vb.w + w010*vc.w + w011*vd.w
                 + w100*ve.w + w101*vf.w + w110*vg.w + w111*vh.w;
        } else {
            int j0 = 4 * c;
            w4.x = (j0     < J) ? g_lbsw_t[(long)(j0    ) * N + n] : 0.0f;
            w4.y = (j0 + 1 < J) ? g_lbsw_t[(long)(j0 + 1) * N + n] : 0.0f;
            w4.z = (j0 + 2 < J) ? g_lbsw_t[(long)(j0 + 2) * N + n] : 0.0f;
            w4.w = (j0 + 3 < J) ? g_lbsw_t[(long)(j0 + 3) * N + n] : 0.0f;
        }
        int t = c * 16;
        ACC(w4.x, t);      ACC(w4.y, t + 4);
        ACC(w4.z, t + 8);  ACC(w4.w, t + 12);
    }

    // xc_cano = w_tf_inv @ [xc, 1]
    float cx = A0.x * px + A0.y * py + A0.z * pz + A0.w;
    float cy = A1.x * px + A1.y * py + A1.z * pz + A1.w;
    float cz = A2.x * px + A2.y * py + A2.z * pz + A2.w;

    // xc_shape = ((xc_cano - poseoff_ori) + shape_offset) + pose_offset
    const long n3 = (long)n * 3, i3 = idx * 3;
    float sx = cx - poseoff_ori[n3 + 0] + shape_off[i3 + 0] + pose_off[i3 + 0];
    float sy = cy - poseoff_ori[n3 + 1] + shape_off[i3 + 1] + pose_off[i3 + 1];
    float sz = cz - poseoff_ori[n3 + 2] + shape_off[i3 + 2] + pose_off[i3 + 2];

    // xd = w_tf @ [xc_shape, 1]  (rows 0..2)
    out_xd[i3 + 0] = C0.x * sx + C0.y * sy + C0.z * sz + C0.w;
    out_xd[i3 + 1] = C1.x * sx + C1.y * sy + C1.z * sz + C1.w;
    out_xd[i3 + 2] = C2.x * sx + C2.y * sy + C2.z * sz + C2.w;

    // w_tf_all = w_tf @ w_tf_inv  (row i = sum_k C[i][k] * Arow_k)
    float4* ow = ((float4*)out_w) + idx * 4;
    float4 R;
    R.x = C0.x*A0.x + C0.y*A1.x + C0.z*A2.x + C0.w*A3.x;
    R.y = C0.x*A0.y + C0.y*A1.y + C0.z*A2.y + C0.w*A3.y;
    R.z = C0.x*A0.z + C0.y*A1.z + C0.z*A2.z + C0.w*A3.z;
    R.w = C0.x*A0.w + C0.y*A1.w + C0.z*A2.w + C0.w*A3.w;
    ow[0] = R;
    R.x = C1.x*A0.x + C1.y*A1.x + C1.z*A2.x + C1.w*A3.x;
    R.y = C1.x*A0.y + C1.y*A1.y + C1.z*A2.y + C1.w*A3.y;
    R.z = C1.x*A0.z + C1.y*A1.z + C1.z*A2.z + C1.w*A3.z;
    R.w = C1.x*A0.w + C1.y*A1.w + C1.z*A2.w + C1.w*A3.w;
    ow[1] = R;
    R.x = C2.x*A0.x + C2.y*A1.x + C2.z*A2.x + C2.w*A3.x;
    R.y = C2.x*A0.y + C2.y*A1.y + C2.z*A2.y + C2.w*A3.y;
    R.z = C2.x*A0.z + C2.y*A1.z + C2.z*A2.z + C2.w*A3.z;
    R.w = C2.x*A0.w + C2.y*A1.w + C2.z*A2.w + C2.w*A3.w;
    ow[2] = R;
    R.x = C3.x*A0.x + C3.y*A1.x + C3.z*A2.x + C3.w*A3.x;
    R.y = C3.x*A0.y + C3.y*A1.y + C3.z*A2.y + C3.w*A3.y;
    R.z = C3.x*A0.z + C3.y*A1.z + C3.z*A2.z + C3.w*A3.z;
    R.w = C3.x*A0.w + C3.y*A1.w + C3.z*A2.w + C3.w*A3.w;
    ow[3] = R;
}

// ---------------------------------------------------------------------------
// Host: resolve inputs by exact element count so the binding is independent of
// metadata ordering (dict order vs alphabetical both handled).
// ---------------------------------------------------------------------------
extern "C" void kernel_launch(void* const* d_in, const int* in_sizes, int n_in,
                              void* d_out, int out_size) {
    // Known element counts for this problem instance:
    //   xc/shape_offset/pose_offset : 3,000,000 (three of these)
    //   tfs: 3520   tfs_inv: 880    poseoff_ori: 750,000
    //   lbsw: 13,750,000   mask: 250,000   lbs_voxel: 3,604,480
    //   offset_kernel / scale_kernel : 3 (offset precedes scale in both
    //   dict and alphabetical orderings)
    const float *tfs = nullptr, *tfs_inv = nullptr, *poseoff_ori = nullptr,
                *lbsw = nullptr, *vol = nullptr;
    const void  *mask = nullptr;
    const float *p3M[3] = {nullptr, nullptr, nullptr};
    const float *psm[2] = {nullptr, nullptr};
    int c3 = 0, cs = 0;
    int idx_mask = -1, idx_first3M = -1;

    for (int i = 0; i < n_in; i++) {
        switch (in_sizes[i]) {
            case 3520:     tfs = (const float*)d_in[i]; break;
            case 880:      tfs_inv = (const float*)d_in[i]; break;
            case 750000:   poseoff_ori = (const float*)d_in[i]; break;
            case 13750000: lbsw = (const float*)d_in[i]; break;
            case 250000:   mask = d_in[i]; idx_mask = i; break;
            case 3604480:  vol = (const float*)d_in[i]; break;
            case 3:        if (cs < 2) psm[cs++] = (const float*)d_in[i]; break;
            case 3000000:
                if (c3 == 0) idx_first3M = i;
                if (c3 < 3) p3M[c3++] = (const float*)d_in[i];
                break;
            default: break;
        }
    }

    const int J = 55, N = 250000, B = 4;

    // xc is first of the 3M group in dict order, last in alphabetical order.
    // In alphabetical order the mask (size 250000) precedes all 3M entries.
    const float* xc        = (idx_mask >= 0 && idx_first3M >= 0 && idx_mask < idx_first3M)
                             ? p3M[2] : p3M[0];
    const float* shape_off = (xc == p3M[0]) ? p3M[1] : p3M[0];
    const float* pose_off  = (xc == p3M[0]) ? p3M[2] : p3M[1];
    const float* offk = psm[0];   // offset_kernel precedes scale_kernel in both orders
    const float* sclk = psm[1];

    float* out_xd = (float*)d_out;
    float* out_w  = out_xd + (size_t)B * N * 3;

    reset_flag_kernel<<<1, 1>>>();
    detect_mask_kernel<<<(65536 + 255) / 256, 256>>>((const unsigned char*)mask, N);
    transpose_vol_kernel<<<NVOX / 64, 256>>>(vol, J);
    transpose_lbsw_kernel<<<(N + 63) / 64, 256>>>(lbsw, N, J);

    dim3 grid((N + 255) / 256, B);
    deform_kernel<<<grid, 256>>>(xc, shape_off, pose_off, tfs, tfs_inv,
                                 poseoff_ori, mask, offk, sclk,
                                 out_xd, out_w, N, J);
}

// round 4
// speedup vs baseline: 1.3442x; 1.3442x over previous
#include <cuda_runtime.h>
#include <cstdint>

#define DV 16
#define HV 64
#define WV 64
#define NVOX (DV*HV*WV)   /* 65536 voxels */
#define JP   64           /* padded channel count (>= J=55) */
#define NMAX 250000

// Scratch (no allocations allowed)
__device__ __align__(16) float g_vol_t[NVOX * JP];     // 16 MB: [voxel][JP]
__device__ __align__(16) float g_lbsw_p[NMAX * JP];    // 64 MB: [n][JP] padded rows
__device__ int g_mask_is_u8;                           // runtime mask-dtype flag

// ---------------------------------------------------------------------------
// mask dtype detection: int32 0/1 has zero bytes at offsets %4!=0; u8 doesn't.
// ---------------------------------------------------------------------------
__global__ void reset_flag_kernel() { g_mask_is_u8 = 0; }

__global__ void detect_mask_kernel(const unsigned char* __restrict__ m, int N) {
    int i = blockIdx.x * 256 + threadIdx.x;
    int limit = N < 65536 ? N : 65536;
    if (i < limit && (i & 3) != 0 && m[i] != 0)
        atomicOr(&g_mask_is_u8, 1);
}

// ---------------------------------------------------------------------------
// Kernel 1: vol [J][D][H][W] -> g_vol_t [D*H*W][JP] (channel-contiguous, padded)
// ---------------------------------------------------------------------------
__global__ void __launch_bounds__(256) transpose_vol_kernel(const float* __restrict__ vol, int J) {
    __shared__ float tile[64][65];
    int v0 = blockIdx.x * 64;
    #pragma unroll
    for (int e = threadIdx.x; e < 64 * 64; e += 256) {
        int j = e >> 6, vi = e & 63;
        tile[j][vi] = (j < J) ? vol[j * NVOX + v0 + vi] : 0.0f;
    }
    __syncthreads();
    #pragma unroll
    for (int e = threadIdx.x; e < 64 * 64; e += 256) {
        int vi = e >> 6, j = e & 63;
        g_vol_t[(v0 + vi) * JP + j] = tile[j][vi];
    }
}

// ---------------------------------------------------------------------------
// Kernel 2: lbsw [N][55] -> g_lbsw_p [N][64] (float4-aligned padded rows)
// ---------------------------------------------------------------------------
__global__ void __launch_bounds__(256) pad_lbsw_kernel(const float* __restrict__ lbsw, int N, int J) {
    long total = (long)N * JP;
    for (long e = (long)blockIdx.x * 256 + threadIdx.x; e < total; e += (long)gridDim.x * 256) {
        int n = (int)(e >> 6), k = (int)(e & 63);
        g_lbsw_p[e] = (k < J) ? lbsw[(long)n * J + k] : 0.0f;
    }
}

// ---------------------------------------------------------------------------
// Kernel 3: fused deformer. 128 threads = 4 warps; each warp owns 32 points.
// Phase 1: cooperative coalesced gather+interp of voxel corners into smem.
//          Per-point corner offsets/weights are staged in smem (raw, all 8);
//          each consuming lane selects its own even/odd corner set locally.
// Phase 2: per-thread blend with tfs/tfs_inv from shared memory.
// ---------------------------------------------------------------------------
static __device__ __forceinline__ float4 fma4(float a, float4 b, float4 c) {
    float4 r;
    r.x = fmaf(a, b.x, c.x); r.y = fmaf(a, b.y, c.y);
    r.z = fmaf(a, b.z, c.z); r.w = fmaf(a, b.w, c.w);
    return r;
}

#define ACC(WJ, T) do { float ww = (WJ);                                      \
    A0 = fma4(ww, s_ti[(T)+0], A0); A1 = fma4(ww, s_ti[(T)+1], A1);           \
    A2 = fma4(ww, s_ti[(T)+2], A2); A3 = fma4(ww, s_ti[(T)+3], A3);           \
    C0 = fma4(ww, s_tf[(T)+0], C0); C1 = fma4(ww, s_tf[(T)+1], C1);           \
    C2 = fma4(ww, s_tf[(T)+2], C2); C3 = fma4(ww, s_tf[(T)+3], C3); } while(0)

#define NWRP 4

__global__ void __launch_bounds__(128) deform_kernel(
    const float* __restrict__ xc, const float* __restrict__ shape_off,
    const float* __restrict__ pose_off, const float* __restrict__ tfs,
    const float* __restrict__ tfs_inv, const float* __restrict__ poseoff_ori,
    const void* __restrict__ mask_raw,
    const float* __restrict__ offk, const float* __restrict__ sclk,
    float* __restrict__ out_xd, float* __restrict__ out_w,
    int N, int J)
{
    const int b = blockIdx.y;
    __shared__ float4 s_ti[56 * 4];            // tfs_inv rows
    __shared__ float4 s_tf[56 * 4];            // tfs[b] rows
    __shared__ float4 s_ws[NWRP][16][33];      // staged weights [warp][chunk][pt]
    __shared__ int    s_po[NWRP][32][9];       // staged corner offsets (pad 9)
    __shared__ float  s_pw[NWRP][32][9];       // staged corner weights (pad 9)

    {
        float* sti = (float*)s_ti;
        float* stf = (float*)s_tf;
        for (int e = threadIdx.x; e < 56 * 16; e += 128) {
            int j = e >> 4, k = e & 15;
            sti[e] = (j < J) ? tfs_inv[j * 16 + k] : 0.0f;
            stf[e] = (j < J) ? tfs[(b * J + j) * 16 + k] : 0.0f;
        }
    }
    __syncthreads();

    const int warp = threadIdx.x >> 5;
    const int lane = threadIdx.x & 31;
    const int n  = (blockIdx.x * NWRP + warp) * 32 + lane;
    const int nc = n < N ? n : N - 1;          // clamp; no early return (warp ops!)
    const long idx = (long)b * N + nc;

    // ----- per-point setup: mask + corner offsets/weights -----
    bool msk;
    if (g_mask_is_u8) msk = (((const unsigned char*)mask_raw)[nc] != 0);
    else              msk = (((const int*)mask_raw)[nc] != 0);
    const unsigned mbits = __ballot_sync(0xffffffffu, msk);

    const float px = xc[idx * 3 + 0], py = xc[idx * 3 + 1], pz = xc[idx * 3 + 2];
    const float fx = (px + offk[0]) * sclk[0];
    const float fy = (py + offk[1]) * sclk[1];
    const float fz = (pz + offk[2]) * sclk[2];

    float ix = fminf(fmaxf((fx + 1.0f) * 0.5f * (float)(WV - 1), 0.0f), (float)(WV - 1));
    float iy = fminf(fmaxf((fy + 1.0f) * 0.5f * (float)(HV - 1), 0.0f), (float)(HV - 1));
    float iz = fminf(fmaxf((fz + 1.0f) * 0.5f * (float)(DV - 1), 0.0f), (float)(DV - 1));
    float xf = floorf(ix), yf = floorf(iy), zf = floorf(iz);
    float wx = ix - xf, wy = iy - yf, wz = iz - zf;
    int x0 = (int)xf, y0 = (int)yf, z0 = (int)zf;
    int x1 = min(x0 + 1, WV - 1), y1 = min(y0 + 1, HV - 1), z1 = min(z0 + 1, DV - 1);

    int r00 = (z0 * HV + y0) * WV, r01 = (z0 * HV + y1) * WV;
    int r10 = (z1 * HV + y0) * WV, r11 = (z1 * HV + y1) * WV;

    float mx = 1.0f - wx, my = 1.0f - wy, mz = 1.0f - wz;

    // Stage raw per-point corner data (offsets in float4 units; 16 f4/voxel).
    {
        int*   po = s_po[warp][lane];
        float* pw = s_pw[warp][lane];
        po[0] = (r00 + x0) * 16;  pw[0] = mz * my * mx;   // 000
        po[1] = (r00 + x1) * 16;  pw[1] = mz * my * wx;   // 001
        po[2] = (r01 + x0) * 16;  pw[2] = mz * wy * mx;   // 010
        po[3] = (r01 + x1) * 16;  pw[3] = mz * wy * wx;   // 011
        po[4] = (r10 + x0) * 16;  pw[4] = wz * my * mx;   // 100
        po[5] = (r10 + x1) * 16;  pw[5] = wz * my * wx;   // 101
        po[6] = (r11 + x0) * 16;  pw[6] = wz * wy * mx;   // 110
        po[7] = (r11 + x1) * 16;  pw[7] = wz * wy * wx;   // 111
    }
    __syncwarp();

    // ----- phase 1: cooperative gather for unmasked points -----
    const float4* vt4 = (const float4*)g_vol_t;
    const int c = lane & 15;          // float4 chunk handled by this lane
    const int half = lane >> 4;       // 0: even corners {0,2,4,6}, 1: odd {1,3,5,7}

    #pragma unroll 2
    for (int p = 0; p < 32; ++p) {
        if ((mbits >> p) & 1u) continue;      // warp-uniform branch
        const int*   po = s_po[warp][p];      // broadcast reads
        const float* pw = s_pw[warp][p];

        float4 acc = make_float4(0.f, 0.f, 0.f, 0.f);
        float4 v;
        v = vt4[po[half + 0] + c]; acc = fma4(pw[half + 0], v, acc);
        v = vt4[po[half + 2] + c]; acc = fma4(pw[half + 2], v, acc);
        v = vt4[po[half + 4] + c]; acc = fma4(pw[half + 4], v, acc);
        v = vt4[po[half + 6] + c]; acc = fma4(pw[half + 6], v, acc);

        // combine even-corner and odd-corner partial sums
        acc.x += __shfl_xor_sync(0xffffffffu, acc.x, 16);
        acc.y += __shfl_xor_sync(0xffffffffu, acc.y, 16);
        acc.z += __shfl_xor_sync(0xffffffffu, acc.z, 16);
        acc.w += __shfl_xor_sync(0xffffffffu, acc.w, 16);
        if (half == 0) s_ws[warp][c][p] = acc;
    }
    __syncwarp();

    // ----- phase 2: per-thread blend -----
    const float4* lb4 = (const float4*)g_lbsw_p + (long)nc * 16;

    float4 A0 = {0,0,0,0}, A1 = {0,0,0,0}, A2 = {0,0,0,0}, A3 = {0,0,0,0};
    float4 C0 = {0,0,0,0}, C1 = {0,0,0,0}, C2 = {0,0,0,0}, C3 = {0,0,0,0};

    #pragma unroll
    for (int cc = 0; cc < 14; ++cc) {
        float4 w4 = msk ? lb4[cc] : s_ws[warp][cc][lane];
        int t = cc * 16;
        ACC(w4.x, t);      ACC(w4.y, t + 4);
        ACC(w4.z, t + 8);  ACC(w4.w, t + 12);
    }

    // xc_cano = w_tf_inv @ [xc, 1]
    float cx = A0.x * px + A0.y * py + A0.z * pz + A0.w;
    float cy = A1.x * px + A1.y * py + A1.z * pz + A1.w;
    float cz = A2.x * px + A2.y * py + A2.z * pz + A2.w;

    const long n3 = (long)nc * 3, i3 = idx * 3;
    float sx = cx - poseoff_ori[n3 + 0] + shape_off[i3 + 0] + pose_off[i3 + 0];
    float sy = cy - poseoff_ori[n3 + 1] + shape_off[i3 + 1] + pose_off[i3 + 1];
    float sz = cz - poseoff_ori[n3 + 2] + shape_off[i3 + 2] + pose_off[i3 + 2];

    if (n < N) {
        out_xd[i3 + 0] = C0.x * sx + C0.y * sy + C0.z * sz + C0.w;
        out_xd[i3 + 1] = C1.x * sx + C1.y * sy + C1.z * sz + C1.w;
        out_xd[i3 + 2] = C2.x * sx + C2.y * sy + C2.z * sz + C2.w;

        float4* ow = ((float4*)out_w) + idx * 4;
        float4 R;
        R.x = C0.x*A0.x + C0.y*A1.x + C0.z*A2.x + C0.w*A3.x;
        R.y = C0.x*A0.y + C0.y*A1.y + C0.z*A2.y + C0.w*A3.y;
        R.z = C0.x*A0.z + C0.y*A1.z + C0.z*A2.z + C0.w*A3.z;
        R.w = C0.x*A0.w + C0.y*A1.w + C0.z*A2.w + C0.w*A3.w;
        ow[0] = R;
        R.x = C1.x*A0.x + C1.y*A1.x + C1.z*A2.x + C1.w*A3.x;
        R.y = C1.x*A0.y + C1.y*A1.y + C1.z*A2.y + C1.w*A3.y;
        R.z = C1.x*A0.z + C1.y*A1.z + C1.z*A2.z + C1.w*A3.z;
        R.w = C1.x*A0.w + C1.y*A1.w + C1.z*A2.w + C1.w*A3.w;
        ow[1] = R;
        R.x = C2.x*A0.x + C2.y*A1.x + C2.z*A2.x + C2.w*A3.x;
        R.y = C2.x*A0.y + C2.y*A1.y + C2.z*A2.y + C2.w*A3.y;
        R.z = C2.x*A0.z + C2.y*A1.z + C2.z*A2.z + C2.w*A3.z;
        R.w = C2.x*A0.w + C2.y*A1.w + C2.z*A2.w + C2.w*A3.w;
        ow[2] = R;
        R.x = C3.x*A0.x + C3.y*A1.x + C3.z*A2.x + C3.w*A3.x;
        R.y = C3.x*A0.y + C3.y*A1.y + C3.z*A2.y + C3.w*A3.y;
        R.z = C3.x*A0.z + C3.y*A1.z + C3.z*A2.z + C3.w*A3.z;
        R.w = C3.x*A0.w + C3.y*A1.w + C3.z*A2.w + C3.w*A3.w;
        ow[3] = R;
    }
}

// ---------------------------------------------------------------------------
// Host: resolve inputs by exact element count (ordering-independent binding).
// ---------------------------------------------------------------------------
extern "C" void kernel_launch(void* const* d_in, const int* in_sizes, int n_in,
                              void* d_out, int out_size) {
    const float *tfs = nullptr, *tfs_inv = nullptr, *poseoff_ori = nullptr,
                *lbsw = nullptr, *vol = nullptr;
    const void  *mask = nullptr;
    const float *p3M[3] = {nullptr, nullptr, nullptr};
    const float *psm[2] = {nullptr, nullptr};
    int c3 = 0, cs = 0;
    int idx_mask = -1, idx_first3M = -1;

    for (int i = 0; i < n_in; i++) {
        switch (in_sizes[i]) {
            case 3520:     tfs = (const float*)d_in[i]; break;
            case 880:      tfs_inv = (const float*)d_in[i]; break;
            case 750000:   poseoff_ori = (const float*)d_in[i]; break;
            case 13750000: lbsw = (const float*)d_in[i]; break;
            case 250000:   mask = d_in[i]; idx_mask = i; break;
            case 3604480:  vol = (const float*)d_in[i]; break;
            case 3:        if (cs < 2) psm[cs++] = (const float*)d_in[i]; break;
            case 3000000:
                if (c3 == 0) idx_first3M = i;
                if (c3 < 3) p3M[c3++] = (const float*)d_in[i];
                break;
            default: break;
        }
    }

    const int J = 55, N = 250000, B = 4;

    const float* xc        = (idx_mask >= 0 && idx_first3M >= 0 && idx_mask < idx_first3M)
                             ? p3M[2] : p3M[0];
    const float* shape_off = (xc == p3M[0]) ? p3M[1] : p3M[0];
    const float* pose_off  = (xc == p3M[0]) ? p3M[2] : p3M[1];
    const float* offk = psm[0];
    const float* sclk = psm[1];

    float* out_xd = (float*)d_out;
    float* out_w  = out_xd + (size_t)B * N * 3;

    reset_flag_kernel<<<1, 1>>>();
    detect_mask_kernel<<<(65536 + 255) / 256, 256>>>((const unsigned char*)mask, N);
    transpose_vol_kernel<<<NVOX / 64, 256>>>(vol, J);
    pad_lbsw_kernel<<<8192, 256>>>(lbsw, N, J);

    dim3 grid((N + 127) / 128, B);
    deform_kernel<<<grid, 128>>>(xc, shape_off, pose_off, tfs, tfs_inv,
                                 poseoff_ori, mask, offk, sclk,
                                 out_xd, out_w, N, J);
}

// round 5
// speedup vs baseline: 1.3875x; 1.0322x over previous
#include <cuda_runtime.h>
#include <cstdint>

#define DV 16
#define HV 64
#define WV 64
#define NVOX (DV*HV*WV)   /* 65536 voxels */
#define JP   64           /* padded channel count (>= J=55) */

// Scratch (no allocations allowed)
__device__ __align__(16) float g_vol_t[NVOX * JP];     // 16 MB: [voxel][JP]
__device__ int g_mask_is_u8;                           // runtime mask-dtype flag

// ---------------------------------------------------------------------------
// mask dtype detection: int32 0/1 has zero bytes at offsets %4!=0; u8 doesn't.
// ---------------------------------------------------------------------------
__global__ void reset_flag_kernel() { g_mask_is_u8 = 0; }

__global__ void detect_mask_kernel(const unsigned char* __restrict__ m, int N) {
    int i = blockIdx.x * 256 + threadIdx.x;
    int limit = N < 65536 ? N : 65536;
    if (i < limit && (i & 3) != 0 && m[i] != 0)
        atomicOr(&g_mask_is_u8, 1);
}

// ---------------------------------------------------------------------------
// Kernel 1: vol [J][D][H][W] -> g_vol_t [D*H*W][JP] (channel-contiguous, padded)
// ---------------------------------------------------------------------------
__global__ void __launch_bounds__(256) transpose_vol_kernel(const float* __restrict__ vol, int J) {
    __shared__ float tile[64][65];
    int v0 = blockIdx.x * 64;
    #pragma unroll
    for (int e = threadIdx.x; e < 64 * 64; e += 256) {
        int j = e >> 6, vi = e & 63;
        tile[j][vi] = (j < J) ? vol[j * NVOX + v0 + vi] : 0.0f;
    }
    __syncthreads();
    #pragma unroll
    for (int e = threadIdx.x; e < 64 * 64; e += 256) {
        int vi = e >> 6, j = e & 63;
        g_vol_t[(v0 + vi) * JP + j] = tile[j][vi];
    }
}

// ---------------------------------------------------------------------------
// packed f32x2 helpers
// ---------------------------------------------------------------------------
static __device__ __forceinline__ unsigned long long ffma2(
    unsigned long long a, unsigned long long b, unsigned long long c) {
    unsigned long long d;
    asm("fma.rn.f32x2 %0, %1, %2, %3;" : "=l"(d) : "l"(a), "l"(b), "l"(c));
    return d;
}
static __device__ __forceinline__ unsigned long long splat2(float w) {
    unsigned long long d;
    asm("mov.b64 %0, {%1, %1};" : "=l"(d) : "f"(w));
    return d;
}
static __device__ __forceinline__ float2 u2f2(unsigned long long v) {
    float2 r;
    asm("mov.b64 {%0, %1}, %2;" : "=f"(r.x), "=f"(r.y) : "l"(v));
    return r;
}
static __device__ __forceinline__ float4 fma4(float a, float4 b, float4 c) {
    float4 r;
    r.x = fmaf(a, b.x, c.x); r.y = fmaf(a, b.y, c.y);
    r.z = fmaf(a, b.z, c.z); r.w = fmaf(a, b.w, c.w);
    return r;
}

// Accumulate weight WW times tfs_inv row-block / tfs row-block (T = j*4 float4s)
#define ACCW(WW, T) do {                                                       \
    unsigned long long w2 = splat2(WW);                                        \
    ulonglong2 ti0 = *(const ulonglong2*)&s_ti[(T)+0];                         \
    ulonglong2 ti1 = *(const ulonglong2*)&s_ti[(T)+1];                         \
    ulonglong2 ti2 = *(const ulonglong2*)&s_ti[(T)+2];                         \
    ulonglong2 ti3 = *(const ulonglong2*)&s_ti[(T)+3];                         \
    A[0]=ffma2(w2,ti0.x,A[0]); A[1]=ffma2(w2,ti0.y,A[1]);                      \
    A[2]=ffma2(w2,ti1.x,A[2]); A[3]=ffma2(w2,ti1.y,A[3]);                      \
    A[4]=ffma2(w2,ti2.x,A[4]); A[5]=ffma2(w2,ti2.y,A[5]);                      \
    A[6]=ffma2(w2,ti3.x,A[6]); A[7]=ffma2(w2,ti3.y,A[7]);                      \
    ulonglong2 tf0 = *(const ulonglong2*)&s_tf[(T)+0];                         \
    ulonglong2 tf1 = *(const ulonglong2*)&s_tf[(T)+1];                         \
    ulonglong2 tf2 = *(const ulonglong2*)&s_tf[(T)+2];                         \
    ulonglong2 tf3 = *(const ulonglong2*)&s_tf[(T)+3];                         \
    C[0]=ffma2(w2,tf0.x,C[0]); C[1]=ffma2(w2,tf0.y,C[1]);                      \
    C[2]=ffma2(w2,tf1.x,C[2]); C[3]=ffma2(w2,tf1.y,C[3]);                      \
    C[4]=ffma2(w2,tf2.x,C[4]); C[5]=ffma2(w2,tf2.y,C[5]);                      \
    C[6]=ffma2(w2,tf3.x,C[6]); C[7]=ffma2(w2,tf3.y,C[7]); } while(0)

#define NWRP 4

// ---------------------------------------------------------------------------
// Kernel 2: fused deformer. 128 threads = 4 warps; each warp owns 32 points.
// Phase 1: per point, cooperative staging of its 55 weights into s_ws:
//          unmasked -> trilinear gather from g_vol_t (coalesced 256B rows)
//          masked   -> direct coalesced scalar load of the lbsw row
// Phase 2: branch-free packed-f32x2 blend with tfs/tfs_inv in shared memory.
// ---------------------------------------------------------------------------
__global__ void __launch_bounds__(128) deform_kernel(
    const float* __restrict__ xc, const float* __restrict__ shape_off,
    const float* __restrict__ pose_off, const float* __restrict__ tfs,
    const float* __restrict__ tfs_inv, const float* __restrict__ poseoff_ori,
    const void* __restrict__ mask_raw, const float* __restrict__ lbsw,
    const float* __restrict__ offk, const float* __restrict__ sclk,
    float* __restrict__ out_xd, float* __restrict__ out_w,
    int N, int J)
{
    const int b = blockIdx.y;
    __shared__ float4 s_ti[56 * 4];            // tfs_inv rows
    __shared__ float4 s_tf[56 * 4];            // tfs[b] rows
    __shared__ float4 s_ws[NWRP][16][33];      // staged weights [warp][chunk][pt]
    __shared__ int    s_po[NWRP][32][9];       // staged corner offsets (pad 9)
    __shared__ float  s_pw[NWRP][32][9];       // staged corner weights (pad 9)

    {
        float* sti = (float*)s_ti;
        float* stf = (float*)s_tf;
        for (int e = threadIdx.x; e < 56 * 16; e += 128) {
            int j = e >> 4, k = e & 15;
            sti[e] = (j < J) ? tfs_inv[j * 16 + k] : 0.0f;
            stf[e] = (j < J) ? tfs[(b * J + j) * 16 + k] : 0.0f;
        }
    }
    __syncthreads();

    const int warp = threadIdx.x >> 5;
    const int lane = threadIdx.x & 31;
    const int wbase = (blockIdx.x * NWRP + warp) * 32;
    const int n  = wbase + lane;
    const int nc = n < N ? n : N - 1;          // clamp; no early return (warp ops!)
    const long idx = (long)b * N + nc;

    // ----- per-point setup: mask + corner offsets/weights -----
    bool msk;
    if (g_mask_is_u8) msk = (((const unsigned char*)mask_raw)[nc] != 0);
    else              msk = (((const int*)mask_raw)[nc] != 0);
    const unsigned mbits = __ballot_sync(0xffffffffu, msk);

    const float px = xc[idx * 3 + 0], py = xc[idx * 3 + 1], pz = xc[idx * 3 + 2];
    const float fx = (px + offk[0]) * sclk[0];
    const float fy = (py + offk[1]) * sclk[1];
    const float fz = (pz + offk[2]) * sclk[2];

    float ix = fminf(fmaxf((fx + 1.0f) * 0.5f * (float)(WV - 1), 0.0f), (float)(WV - 1));
    float iy = fminf(fmaxf((fy + 1.0f) * 0.5f * (float)(HV - 1), 0.0f), (float)(HV - 1));
    float iz = fminf(fmaxf((fz + 1.0f) * 0.5f * (float)(DV - 1), 0.0f), (float)(DV - 1));
    float xf = floorf(ix), yf = floorf(iy), zf = floorf(iz);
    float wx = ix - xf, wy = iy - yf, wz = iz - zf;
    int x0 = (int)xf, y0 = (int)yf, z0 = (int)zf;
    int x1 = min(x0 + 1, WV - 1), y1 = min(y0 + 1, HV - 1), z1 = min(z0 + 1, DV - 1);

    int r00 = (z0 * HV + y0) * WV, r01 = (z0 * HV + y1) * WV;
    int r10 = (z1 * HV + y0) * WV, r11 = (z1 * HV + y1) * WV;
    float mx = 1.0f - wx, my = 1.0f - wy, mz = 1.0f - wz;

    {   // stage raw corner data (offsets in float4 units; 16 f4/voxel)
        int*   po = s_po[warp][lane];
        float* pw = s_pw[warp][lane];
        po[0] = (r00 + x0) * 16;  pw[0] = mz * my * mx;
        po[1] = (r00 + x1) * 16;  pw[1] = mz * my * wx;
        po[2] = (r01 + x0) * 16;  pw[2] = mz * wy * mx;
        po[3] = (r01 + x1) * 16;  pw[3] = mz * wy * wx;
        po[4] = (r10 + x0) * 16;  pw[4] = wz * my * mx;
        po[5] = (r10 + x1) * 16;  pw[5] = wz * my * wx;
        po[6] = (r11 + x0) * 16;  pw[6] = wz * wy * mx;
        po[7] = (r11 + x1) * 16;  pw[7] = wz * wy * wx;
    }
    __syncwarp();

    // ----- phase 1: stage all 32 points' weights into s_ws -----
    const float4* vt4 = (const float4*)g_vol_t;
    float* wsf = (float*)s_ws[warp];            // scalar view: ((j>>2)*33+p)*4+(j&3)
    const int c = lane & 15;
    const int half = lane >> 4;                 // 0: corners {0,2,4,6}, 1: {1,3,5,7}
    const int j1 = lane, j2 = lane + 32;        // scalar lanes for masked rows
    const int i1 = ((j1 >> 2) * 33) * 4 + (j1 & 3);
    const int i2 = ((j2 >> 2) * 33) * 4 + (j2 & 3);

    #pragma unroll 2
    for (int p = 0; p < 32; ++p) {
        if ((mbits >> p) & 1u) {
            // masked: coalesced scalar load of lbsw row (220 B, 4B-aligned)
            int np = wbase + p;
            if (np >= N) continue;
            const float* row = lbsw + (long)np * J;
            wsf[i1 + p * 4] = (j1 < J) ? row[j1] : 0.0f;
            wsf[i2 + p * 4] = (j2 < J) ? row[j2] : 0.0f;
        } else {
            // unmasked: cooperative trilinear gather
            const int*   po = s_po[warp][p];    // broadcast reads
            const float* pw = s_pw[warp][p];
            float4 acc = make_float4(0.f, 0.f, 0.f, 0.f);
            float4 v;
            v = vt4[po[half + 0] + c]; acc = fma4(pw[half + 0], v, acc);
            v = vt4[po[half + 2] + c]; acc = fma4(pw[half + 2], v, acc);
            v = vt4[po[half + 4] + c]; acc = fma4(pw[half + 4], v, acc);
            v = vt4[po[half + 6] + c]; acc = fma4(pw[half + 6], v, acc);
            acc.x += __shfl_xor_sync(0xffffffffu, acc.x, 16);
            acc.y += __shfl_xor_sync(0xffffffffu, acc.y, 16);
            acc.z += __shfl_xor_sync(0xffffffffu, acc.z, 16);
            acc.w += __shfl_xor_sync(0xffffffffu, acc.w, 16);
            if (half == 0) s_ws[warp][c][p] = acc;
        }
    }
    __syncwarp();

    // ----- phase 2: branch-free packed-f32x2 blend -----
    unsigned long long A[8], C[8];
    #pragma unroll
    for (int i = 0; i < 8; ++i) { A[i] = 0ull; C[i] = 0ull; }

    #pragma unroll
    for (int cc = 0; cc < 14; ++cc) {
        float4 w4 = s_ws[warp][cc][lane];
        int t = cc * 16;
        ACCW(w4.x, t);      ACCW(w4.y, t + 4);
        ACCW(w4.z, t + 8);  ACCW(w4.w, t + 12);
    }

    float2 a0l = u2f2(A[0]), a0h = u2f2(A[1]);
    float2 a1l = u2f2(A[2]), a1h = u2f2(A[3]);
    float2 a2l = u2f2(A[4]), a2h = u2f2(A[5]);
    float2 a3l = u2f2(A[6]), a3h = u2f2(A[7]);
    float4 A0 = {a0l.x, a0l.y, a0h.x, a0h.y};
    float4 A1 = {a1l.x, a1l.y, a1h.x, a1h.y};
    float4 A2 = {a2l.x, a2l.y, a2h.x, a2h.y};
    float4 A3 = {a3l.x, a3l.y, a3h.x, a3h.y};
    float2 c0l = u2f2(C[0]), c0h = u2f2(C[1]);
    float2 c1l = u2f2(C[2]), c1h = u2f2(C[3]);
    float2 c2l = u2f2(C[4]), c2h = u2f2(C[5]);
    float2 c3l = u2f2(C[6]), c3h = u2f2(C[7]);
    float4 C0 = {c0l.x, c0l.y, c0h.x, c0h.y};
    float4 C1 = {c1l.x, c1l.y, c1h.x, c1h.y};
    float4 C2 = {c2l.x, c2l.y, c2h.x, c2h.y};
    float4 C3 = {c3l.x, c3l.y, c3h.x, c3h.y};

    // xc_cano = w_tf_inv @ [xc, 1]
    float cx = A0.x * px + A0.y * py + A0.z * pz + A0.w;
    float cy = A1.x * px + A1.y * py + A1.z * pz + A1.w;
    float cz = A2.x * px + A2.y * py + A2.z * pz + A2.w;

    const long n3 = (long)nc * 3, i3 = idx * 3;
    float sx = cx - poseoff_ori[n3 + 0] + shape_off[i3 + 0] + pose_off[i3 + 0];
    float sy = cy - poseoff_ori[n3 + 1] + shape_off[i3 + 1] + pose_off[i3 + 1];
    float sz = cz - poseoff_ori[n3 + 2] + shape_off[i3 + 2] + pose_off[i3 + 2];

    if (n < N) {
        out_xd[i3 + 0] = C0.x * sx + C0.y * sy + C0.z * sz + C0.w;
        out_xd[i3 + 1] = C1.x * sx + C1.y * sy + C1.z * sz + C1.w;
        out_xd[i3 + 2] = C2.x * sx + C2.y * sy + C2.z * sz + C2.w;

        float4* ow = ((float4*)out_w) + idx * 4;
        float4 R;
        R.x = C0.x*A0.x + C0.y*A1.x + C0.z*A2.x + C0.w*A3.x;
        R.y = C0.x*A0.y + C0.y*A1.y + C0.z*A2.y + C0.w*A3.y;
        R.z = C0.x*A0.z + C0.y*A1.z + C0.z*A2.z + C0.w*A3.z;
        R.w = C0.x*A0.w + C0.y*A1.w + C0.z*A2.w + C0.w*A3.w;
        ow[0] = R;
        R.x = C1.x*A0.x + C1.y*A1.x + C1.z*A2.x + C1.w*A3.x;
        R.y = C1.x*A0.y + C1.y*A1.y + C1.z*A2.y + C1.w*A3.y;
        R.z = C1.x*A0.z + C1.y*A1.z + C1.z*A2.z + C1.w*A3.z;
        R.w = C1.x*A0.w + C1.y*A1.w + C1.z*A2.w + C1.w*A3.w;
        ow[1] = R;
        R.x = C2.x*A0.x + C2.y*A1.x + C2.z*A2.x + C2.w*A3.x;
        R.y = C2.x*A0.y + C2.y*A1.y + C2.z*A2.y + C2.w*A3.y;
        R.z = C2.x*A0.z + C2.y*A1.z + C2.z*A2.z + C2.w*A3.z;
        R.w = C2.x*A0.w + C2.y*A1.w + C2.z*A2.w + C2.w*A3.w;
        ow[2] = R;
        R.x = C3.x*A0.x + C3.y*A1.x + C3.z*A2.x + C3.w*A3.x;
        R.y = C3.x*A0.y + C3.y*A1.y + C3.z*A2.y + C3.w*A3.y;
        R.z = C3.x*A0.z + C3.y*A1.z + C3.z*A2.z + C3.w*A3.z;
        R.w = C3.x*A0.w + C3.y*A1.w + C3.z*A2.w + C3.w*A3.w;
        ow[3] = R;
    }
}

// ---------------------------------------------------------------------------
// Host: resolve inputs by exact element count (ordering-independent binding).
// ---------------------------------------------------------------------------
extern "C" void kernel_launch(void* const* d_in, const int* in_sizes, int n_in,
                              void* d_out, int out_size) {
    const float *tfs = nullptr, *tfs_inv = nullptr, *poseoff_ori = nullptr,
                *lbsw = nullptr, *vol = nullptr;
    const void  *mask = nullptr;
    const float *p3M[3] = {nullptr, nullptr, nullptr};
    const float *psm[2] = {nullptr, nullptr};
    int c3 = 0, cs = 0;
    int idx_mask = -1, idx_first3M = -1;

    for (int i = 0; i < n_in; i++) {
        switch (in_sizes[i]) {
            case 3520:     tfs = (const float*)d_in[i]; break;
            case 880:      tfs_inv = (const float*)d_in[i]; break;
            case 750000:   poseoff_ori = (const float*)d_in[i]; break;
            case 13750000: lbsw = (const float*)d_in[i]; break;
            case 250000:   mask = d_in[i]; idx_mask = i; break;
            case 3604480:  vol = (const float*)d_in[i]; break;
            case 3:        if (cs < 2) psm[cs++] = (const float*)d_in[i]; break;
            case 3000000:
                if (c3 == 0) idx_first3M = i;
                if (c3 < 3) p3M[c3++] = (const float*)d_in[i];
                break;
            default: break;
        }
    }

    const int J = 55, N = 250000, B = 4;

    const float* xc        = (idx_mask >= 0 && idx_first3M >= 0 && idx_mask < idx_first3M)
                             ? p3M[2] : p3M[0];
    const float* shape_off = (xc == p3M[0]) ? p3M[1] : p3M[0];
    const float* pose_off  = (xc == p3M[0]) ? p3M[2] : p3M[1];
    const float* offk = psm[0];
    const float* sclk = psm[1];

    float* out_xd = (float*)d_out;
    float* out_w  = out_xd + (size_t)B * N * 3;

    reset_flag_kernel<<<1, 1>>>();
    detect_mask_kernel<<<(65536 + 255) / 256, 256>>>((const unsigned char*)mask, N);
    transpose_vol_kernel<<<NVOX / 64, 256>>>(vol, J);

    dim3 grid((N + 127) / 128, B);
    deform_kernel<<<grid, 128>>>(xc, shape_off, pose_off, tfs, tfs_inv,
                                 poseoff_ori, mask, lbsw, offk, sclk,
                                 out_xd, out_w, N, J);
}